// round 1
// baseline (speedup 1.0000x reference)
#include <cuda_runtime.h>
#include <cuda_bf16.h>

#define NLAYER 4
#define HID    1024
#define BATCH  64
#define NSTEP  128
#define GDIM   4096              // 4*HID
#define TBROWS (NSTEP*BATCH)     // 8192

// ---------------- device scratch (static: no allocation allowed) ----------------
// Split bf16 weights, gate-interleaved and N-major: W[l][j'][k], j' = unit*4 + gate
__device__ __nv_bfloat16 g_wi_hi[(size_t)NLAYER*GDIM*HID];
__device__ __nv_bfloat16 g_wi_lo[(size_t)NLAYER*GDIM*HID];
__device__ __nv_bfloat16 g_wh_hi[(size_t)NLAYER*GDIM*HID];
__device__ __nv_bfloat16 g_wh_lo[(size_t)NLAYER*GDIM*HID];
__device__ float g_bias[NLAYER*GDIM];            // gate-interleaved bias
__device__ float g_gpre[(size_t)TBROWS*GDIM];    // x@Wi + b for current layer
__device__ float g_seq[2][(size_t)NSTEP*BATCH*HID]; // per-layer h sequences (ping-pong)
__device__ float g_c[BATCH*HID];                 // cell state of current layer

// ---------------- mma helper: m16n8k16 bf16, fp32 accum ----------------
__device__ __forceinline__ void mma_bf16(float (&c)[4], const unsigned (&a)[4],
                                         const unsigned (&b)[2]) {
    asm volatile(
        "mma.sync.aligned.m16n8k16.row.col.f32.bf16.bf16.f32 "
        "{%0,%1,%2,%3}, {%4,%5,%6,%7}, {%8,%9}, {%0,%1,%2,%3};\n"
        : "+f"(c[0]), "+f"(c[1]), "+f"(c[2]), "+f"(c[3])
        : "r"(a[0]), "r"(a[1]), "r"(a[2]), "r"(a[3]), "r"(b[0]), "r"(b[1]));
}

// ---------------- weight prep: fp32 -> split bf16, transpose + gate interleave ----
// grid (GDIM/32, HID/32, NLAYER*2), block (32,32)
__global__ void prep_weights_kernel(const float* __restrict__ Wi,
                                    const float* __restrict__ Wh) {
    __shared__ float tile[32][33];
    int l = blockIdx.z & 3;
    int which = blockIdx.z >> 2;                  // 0 = Wi, 1 = Wh
    const float* W = which ? Wh : Wi;
    __nv_bfloat16* ohi = which ? g_wh_hi : g_wi_hi;
    __nv_bfloat16* olo = which ? g_wh_lo : g_wi_lo;
    int j0 = blockIdx.x * 32, k0 = blockIdx.y * 32;
    int tx = threadIdx.x, ty = threadIdx.y;
    tile[ty][tx] = W[(size_t)(l * HID + k0 + ty) * GDIM + j0 + tx];
    __syncthreads();
    float v = tile[tx][ty];                        // = W[k0+tx][j0+ty]
    int j = j0 + ty;
    int gate = j >> 10, unit = j & 1023;
    int jp = unit * 4 + gate;                      // interleaved column
    __nv_bfloat16 hi = __float2bfloat16(v);
    float lov = v - __bfloat162float(hi);
    size_t o = (size_t)(l * GDIM + jp) * HID + (k0 + tx);
    ohi[o] = hi;
    olo[o] = __float2bfloat16(lov);
}

__global__ void prep_bias_kernel(const float* __restrict__ b) {
    int i = blockIdx.x * 256 + threadIdx.x;        // NLAYER*GDIM = 16384
    if (i < NLAYER * GDIM) {
        int l = i >> 12, j = i & 4095;
        int gate = j >> 10, unit = j & 1023;
        g_bias[l * GDIM + unit * 4 + gate] = b[i];
    }
}

// ---------------- pre-GEMM: gpre = X @ Wi' + b'  (M=8192, N=4096, K=1024) -------
// CTA tile 128x64, 8 warps (4x2), warp tile 32x32, KC=32
__global__ __launch_bounds__(256, 1)
void pregemm_kernel(const float* __restrict__ X0, int layer) {
    __shared__ __align__(16) __nv_bfloat16 sAh[128 * 40];
    __shared__ __align__(16) __nv_bfloat16 sAl[128 * 40];
    __shared__ __align__(16) __nv_bfloat16 sBh[64 * 40];
    __shared__ __align__(16) __nv_bfloat16 sBl[64 * 40];

    const float* X = (layer == 0) ? X0 : g_seq[(layer - 1) & 1];
    const __nv_bfloat16* Wh_ = g_wi_hi + (size_t)layer * GDIM * HID;
    const __nv_bfloat16* Wl_ = g_wi_lo + (size_t)layer * GDIM * HID;

    int m0 = blockIdx.y * 128, n0 = blockIdx.x * 64;
    int tid = threadIdx.x, warp = tid >> 5, lane = tid & 31;
    int wm = (warp >> 1) * 32, wn = (warp & 1) * 32;
    int r = lane >> 2, q = lane & 3;

    float acc[2][4][4];
#pragma unroll
    for (int a = 0; a < 2; a++)
#pragma unroll
        for (int b = 0; b < 4; b++)
#pragma unroll
            for (int c = 0; c < 4; c++) acc[a][b][c] = 0.f;

    for (int k0 = 0; k0 < HID; k0 += 32) {
#pragma unroll
        for (int i = tid; i < 128 * 32; i += 256) {
            int rr = i >> 5, kk = i & 31;
            float v = X[(size_t)(m0 + rr) * HID + k0 + kk];
            __nv_bfloat16 hi = __float2bfloat16(v);
            sAh[rr * 40 + kk] = hi;
            sAl[rr * 40 + kk] = __float2bfloat16(v - __bfloat162float(hi));
        }
#pragma unroll
        for (int i = tid; i < 64 * 32; i += 256) {
            int nn = i >> 5, kk = i & 31;
            size_t off = (size_t)(n0 + nn) * HID + k0 + kk;
            sBh[nn * 40 + kk] = Wh_[off];
            sBl[nn * 40 + kk] = Wl_[off];
        }
        __syncthreads();
#pragma unroll
        for (int kk = 0; kk < 32; kk += 16) {
            unsigned ah[2][4], al[2][4], bh[4][2], bl[4][2];
#pragma unroll
            for (int mi = 0; mi < 2; mi++) {
                int rowa = wm + mi * 16 + r;
                const __nv_bfloat16* p = &sAh[rowa * 40 + kk + 2 * q];
                ah[mi][0] = *(const unsigned*)p;
                ah[mi][1] = *(const unsigned*)(p + 8 * 40);
                ah[mi][2] = *(const unsigned*)(p + 8);
                ah[mi][3] = *(const unsigned*)(p + 8 * 40 + 8);
                const __nv_bfloat16* pl = &sAl[rowa * 40 + kk + 2 * q];
                al[mi][0] = *(const unsigned*)pl;
                al[mi][1] = *(const unsigned*)(pl + 8 * 40);
                al[mi][2] = *(const unsigned*)(pl + 8);
                al[mi][3] = *(const unsigned*)(pl + 8 * 40 + 8);
            }
#pragma unroll
            for (int ni = 0; ni < 4; ni++) {
                int rowb = wn + ni * 8 + r;
                const __nv_bfloat16* p = &sBh[rowb * 40 + kk + 2 * q];
                bh[ni][0] = *(const unsigned*)p;
                bh[ni][1] = *(const unsigned*)(p + 8);
                const __nv_bfloat16* pl = &sBl[rowb * 40 + kk + 2 * q];
                bl[ni][0] = *(const unsigned*)pl;
                bl[ni][1] = *(const unsigned*)(pl + 8);
            }
#pragma unroll
            for (int mi = 0; mi < 2; mi++)
#pragma unroll
                for (int ni = 0; ni < 4; ni++) {
                    mma_bf16(acc[mi][ni], ah[mi], bh[ni]);
                    mma_bf16(acc[mi][ni], ah[mi], bl[ni]);
                    mma_bf16(acc[mi][ni], al[mi], bh[ni]);
                }
        }
        __syncthreads();
    }
    const float* bias = g_bias + layer * GDIM;
#pragma unroll
    for (int mi = 0; mi < 2; mi++)
#pragma unroll
        for (int ni = 0; ni < 4; ni++) {
            int gm = m0 + wm + mi * 16 + r;
            int gn = n0 + wn + ni * 8 + 2 * q;
            float b0v = bias[gn], b1v = bias[gn + 1];
            g_gpre[(size_t)gm * GDIM + gn]           = acc[mi][ni][0] + b0v;
            g_gpre[(size_t)gm * GDIM + gn + 1]       = acc[mi][ni][1] + b1v;
            g_gpre[(size_t)(gm + 8) * GDIM + gn]     = acc[mi][ni][2] + b0v;
            g_gpre[(size_t)(gm + 8) * GDIM + gn + 1] = acc[mi][ni][3] + b1v;
        }
}

// ---------------- recurrent step: gates = gpre[t] + h@Wh', then LSTM ------------
// grid GDIM/32 = 128 CTAs; CTA tile 64(batch) x 32(gate cols); 8 warps (4x2) 16x16
__global__ __launch_bounds__(256, 1)
void lstm_step_kernel(int layer, int t) {
    __shared__ __align__(16) __nv_bfloat16 sAh[64 * 72];
    __shared__ __align__(16) __nv_bfloat16 sAl[64 * 72];
    __shared__ __align__(16) __nv_bfloat16 sBh[32 * 72];
    __shared__ __align__(16) __nv_bfloat16 sBl[32 * 72];
    __shared__ float sG[64 * 33];

    float* seq = g_seq[layer & 1];
    const float* hprev = seq + (size_t)(t - 1) * BATCH * HID;  // only read if t>0
    float* hout = seq + (size_t)t * BATCH * HID;

    int n0 = blockIdx.x * 32;
    int tid = threadIdx.x, warp = tid >> 5, lane = tid & 31;
    int wm = (warp >> 1) * 16, wn = (warp & 1) * 16;
    int r = lane >> 2, q = lane & 3;

    float acc[2][4];
#pragma unroll
    for (int a = 0; a < 2; a++)
#pragma unroll
        for (int c = 0; c < 4; c++) acc[a][c] = 0.f;

    if (t > 0) {
        const __nv_bfloat16* Wh_ = g_wh_hi + (size_t)layer * GDIM * HID;
        const __nv_bfloat16* Wl_ = g_wh_lo + (size_t)layer * GDIM * HID;
        for (int k0 = 0; k0 < HID; k0 += 64) {
#pragma unroll
            for (int i = tid; i < 64 * 64; i += 256) {
                int rr = i >> 6, kk = i & 63;
                float v = hprev[(size_t)rr * HID + k0 + kk];
                __nv_bfloat16 hi = __float2bfloat16(v);
                sAh[rr * 72 + kk] = hi;
                sAl[rr * 72 + kk] = __float2bfloat16(v - __bfloat162float(hi));
            }
#pragma unroll
            for (int i = tid; i < 32 * 64; i += 256) {
                int nn = i >> 6, kk = i & 63;
                size_t off = (size_t)(n0 + nn) * HID + k0 + kk;
                sBh[nn * 72 + kk] = Wh_[off];
                sBl[nn * 72 + kk] = Wl_[off];
            }
            __syncthreads();
#pragma unroll
            for (int kk = 0; kk < 64; kk += 16) {
                unsigned ah[4], al[4], bh[2][2], bl[2][2];
                int rowa = wm + r;
                const __nv_bfloat16* p = &sAh[rowa * 72 + kk + 2 * q];
                ah[0] = *(const unsigned*)p;
                ah[1] = *(const unsigned*)(p + 8 * 72);
                ah[2] = *(const unsigned*)(p + 8);
                ah[3] = *(const unsigned*)(p + 8 * 72 + 8);
                const __nv_bfloat16* pl = &sAl[rowa * 72 + kk + 2 * q];
                al[0] = *(const unsigned*)pl;
                al[1] = *(const unsigned*)(pl + 8 * 72);
                al[2] = *(const unsigned*)(pl + 8);
                al[3] = *(const unsigned*)(pl + 8 * 72 + 8);
#pragma unroll
                for (int ni = 0; ni < 2; ni++) {
                    int rowb = wn + ni * 8 + r;
                    const __nv_bfloat16* pb = &sBh[rowb * 72 + kk + 2 * q];
                    bh[ni][0] = *(const unsigned*)pb;
                    bh[ni][1] = *(const unsigned*)(pb + 8);
                    const __nv_bfloat16* pbl = &sBl[rowb * 72 + kk + 2 * q];
                    bl[ni][0] = *(const unsigned*)pbl;
                    bl[ni][1] = *(const unsigned*)(pbl + 8);
                }
#pragma unroll
                for (int ni = 0; ni < 2; ni++) {
                    mma_bf16(acc[ni], ah, bh[ni]);
                    mma_bf16(acc[ni], ah, bl[ni]);
                    mma_bf16(acc[ni], al, bh[ni]);
                }
            }
            __syncthreads();
        }
    }

    // dump warp accumulators into sG (64 batches x 32 gate-cols, padded stride 33)
#pragma unroll
    for (int ni = 0; ni < 2; ni++) {
        int col = wn + ni * 8 + 2 * q;
        sG[(wm + r) * 33 + col]         = acc[ni][0];
        sG[(wm + r) * 33 + col + 1]     = acc[ni][1];
        sG[(wm + r + 8) * 33 + col]     = acc[ni][2];
        sG[(wm + r + 8) * 33 + col + 1] = acc[ni][3];
    }
    __syncthreads();

    // fused LSTM elementwise: this CTA owns hidden units [n0/4, n0/4+8)
    const float* gpre = g_gpre + (size_t)t * BATCH * GDIM;
#pragma unroll
    for (int i = tid; i < 512; i += 256) {
        int b_ = i >> 3, u = i & 7;
        int colb = u * 4;
        const float* gp = gpre + (size_t)b_ * GDIM + n0 + colb;
        float gi = sG[b_ * 33 + colb + 0] + gp[0];
        float gf = sG[b_ * 33 + colb + 1] + gp[1];
        float gg = sG[b_ * 33 + colb + 2] + gp[2];
        float go = sG[b_ * 33 + colb + 3] + gp[3];
        int unit = (n0 >> 2) + u;
        float cold = (t == 0) ? 0.f : g_c[b_ * HID + unit];
        float si = 1.f / (1.f + expf(-gi));
        float sf = 1.f / (1.f + expf(-gf));
        float so = 1.f / (1.f + expf(-go));
        float cn = sf * cold + si * tanhf(gg);
        float hn = so * tanhf(cn);
        g_c[b_ * HID + unit] = cn;
        hout[(size_t)b_ * HID + unit] = hn;
    }
}

// ---------------- finalize: out = [h_last ; h_last ; c_last] --------------------
__global__ void finalize_kernel(float* __restrict__ out) {
    int i = blockIdx.x * 256 + threadIdx.x;
    if (i < BATCH * HID) {
        float hv = g_seq[(NLAYER - 1) & 1][(size_t)(NSTEP - 1) * BATCH * HID + i];
        out[i] = hv;
        out[BATCH * HID + i] = hv;
        out[2 * BATCH * HID + i] = g_c[i];
    }
}

// ---------------- launch --------------------------------------------------------
extern "C" void kernel_launch(void* const* d_in, const int* in_sizes, int n_in,
                              void* d_out, int out_size) {
    (void)in_sizes; (void)n_in; (void)out_size;
    const float* inputs = (const float*)d_in[0];   // [T,B,H]
    const float* Wi     = (const float*)d_in[1];   // [L,H,4H]
    const float* Wh     = (const float*)d_in[2];   // [L,H,4H]
    const float* bv     = (const float*)d_in[3];   // [L,4H]

    dim3 pb(32, 32, 1);
    dim3 pg(GDIM / 32, HID / 32, NLAYER * 2);
    prep_weights_kernel<<<pg, pb>>>(Wi, Wh);
    prep_bias_kernel<<<(NLAYER * GDIM + 255) / 256, 256>>>(bv);

    for (int l = 0; l < NLAYER; l++) {
        pregemm_kernel<<<dim3(GDIM / 64, TBROWS / 128), 256>>>(inputs, l);
        for (int t = 0; t < NSTEP; t++)
            lstm_step_kernel<<<GDIM / 32, 256>>>(l, t);
    }
    finalize_kernel<<<(BATCH * HID + 255) / 256, 256>>>((float*)d_out);
}

// round 2
// speedup vs baseline: 1.5636x; 1.5636x over previous
#include <cuda_runtime.h>
#include <cuda_bf16.h>

#define NLAYER 4
#define HID    1024
#define BATCH  64
#define NSTEP  128
#define GDIM   4096              // 4*HID
#define TBROWS (NSTEP*BATCH)     // 8192

// ---------------- device scratch ----------------
__device__ __nv_bfloat16 g_wi_hi[(size_t)NLAYER*GDIM*HID];
__device__ __nv_bfloat16 g_wi_lo[(size_t)NLAYER*GDIM*HID];
__device__ __nv_bfloat16 g_wh_hi[(size_t)NLAYER*GDIM*HID];
__device__ __nv_bfloat16 g_wh_lo[(size_t)NLAYER*GDIM*HID];
__device__ float g_bias[NLAYER*GDIM];
__device__ float g_gpre[(size_t)TBROWS*GDIM];
__device__ __nv_bfloat16 g_xh[(size_t)TBROWS*HID];   // split input
__device__ __nv_bfloat16 g_xl[(size_t)TBROWS*HID];
__device__ __nv_bfloat16 g_sh[2][(size_t)TBROWS*HID]; // split h sequences (ping-pong by layer)
__device__ __nv_bfloat16 g_sl[2][(size_t)TBROWS*HID];
__device__ float g_c[BATCH*HID];

// ---------------- helpers ----------------
__device__ __forceinline__ void mma_bf16(float (&c)[4], const unsigned (&a)[4],
                                         const unsigned (&b)[2]) {
    asm volatile(
        "mma.sync.aligned.m16n8k16.row.col.f32.bf16.bf16.f32 "
        "{%0,%1,%2,%3}, {%4,%5,%6,%7}, {%8,%9}, {%0,%1,%2,%3};\n"
        : "+f"(c[0]), "+f"(c[1]), "+f"(c[2]), "+f"(c[3])
        : "r"(a[0]), "r"(a[1]), "r"(a[2]), "r"(a[3]), "r"(b[0]), "r"(b[1]));
}

__device__ __forceinline__ void cpasync16(__nv_bfloat16* sptr, const __nv_bfloat16* gptr) {
    unsigned s = (unsigned)__cvta_generic_to_shared(sptr);
    asm volatile("cp.async.cg.shared.global [%0], [%1], 16;\n" :: "r"(s), "l"(gptr));
}
#define CP_COMMIT() asm volatile("cp.async.commit_group;\n")
#define CP_WAIT1()  asm volatile("cp.async.wait_group 1;\n")

// ---------------- weight prep: fp32 -> split bf16, transpose + gate interleave ----
__global__ void prep_weights_kernel(const float* __restrict__ Wi,
                                    const float* __restrict__ Wh) {
    __shared__ float tile[32][33];
    int l = blockIdx.z & 3;
    int which = blockIdx.z >> 2;
    const float* W = which ? Wh : Wi;
    __nv_bfloat16* ohi = which ? g_wh_hi : g_wi_hi;
    __nv_bfloat16* olo = which ? g_wh_lo : g_wi_lo;
    int j0 = blockIdx.x * 32, k0 = blockIdx.y * 32;
    int tx = threadIdx.x, ty = threadIdx.y;
    tile[ty][tx] = W[(size_t)(l * HID + k0 + ty) * GDIM + j0 + tx];
    __syncthreads();
    float v = tile[tx][ty];
    int j = j0 + ty;
    int gate = j >> 10, unit = j & 1023;
    int jp = unit * 4 + gate;
    __nv_bfloat16 hi = __float2bfloat16(v);
    float lov = v - __bfloat162float(hi);
    size_t o = (size_t)(l * GDIM + jp) * HID + (k0 + tx);
    ohi[o] = hi;
    olo[o] = __float2bfloat16(lov);
}

__global__ void prep_bias_kernel(const float* __restrict__ b) {
    int i = blockIdx.x * 256 + threadIdx.x;
    if (i < NLAYER * GDIM) {
        int l = i >> 12, j = i & 4095;
        int gate = j >> 10, unit = j & 1023;
        g_bias[l * GDIM + unit * 4 + gate] = b[i];
    }
}

__global__ void split_input_kernel(const float* __restrict__ X) {
    int i = blockIdx.x * 256 + threadIdx.x;
    if (i < TBROWS * HID) {
        float v = X[i];
        __nv_bfloat16 hi = __float2bfloat16(v);
        g_xh[i] = hi;
        g_xl[i] = __float2bfloat16(v - __bfloat162float(hi));
    }
}

// ---------------- pre-GEMM: gpre = X @ Wi' + b'  (M=8192, N=4096, K=1024) -------
// CTA 128x128, 8 warps (2m x 4n), warp 64x32, KC=32, 3-stage cp.async
#define PG_STG 3
#define PG_AS  (128*40)
#define PG_BS  (128*40)
#define PG_SMEM ((2*PG_STG*PG_AS + 2*PG_STG*PG_BS) * 2)

__device__ __forceinline__ void pg_issue(
    const __nv_bfloat16* Ah, const __nv_bfloat16* Al,
    const __nv_bfloat16* Bh, const __nv_bfloat16* Bl,
    __nv_bfloat16* dAh, __nv_bfloat16* dAl, __nv_bfloat16* dBh, __nv_bfloat16* dBl,
    int m0, int n0, int k0, int tid)
{
#pragma unroll
    for (int i = tid; i < 512; i += 256) {
        int rr = i >> 2, c = i & 3;
        size_t go = (size_t)(m0 + rr) * HID + k0 + c * 8;
        int so = rr * 40 + c * 8;
        cpasync16(dAh + so, Ah + go);
        cpasync16(dAl + so, Al + go);
    }
#pragma unroll
    for (int i = tid; i < 512; i += 256) {
        int rr = i >> 2, c = i & 3;
        size_t go = (size_t)(n0 + rr) * HID + k0 + c * 8;
        int so = rr * 40 + c * 8;
        cpasync16(dBh + so, Bh + go);
        cpasync16(dBl + so, Bl + go);
    }
}

__global__ __launch_bounds__(256, 1)
void pregemm_kernel(int layer) {
    extern __shared__ __nv_bfloat16 sm[];
    __nv_bfloat16* sAh = sm;
    __nv_bfloat16* sAl = sAh + PG_STG * PG_AS;
    __nv_bfloat16* sBh = sAl + PG_STG * PG_AS;
    __nv_bfloat16* sBl = sBh + PG_STG * PG_BS;

    const __nv_bfloat16 *Ah, *Al;
    if (layer == 0) { Ah = g_xh; Al = g_xl; }
    else { Ah = g_sh[(layer - 1) & 1]; Al = g_sl[(layer - 1) & 1]; }
    const __nv_bfloat16* Bh = g_wi_hi + (size_t)layer * GDIM * HID;
    const __nv_bfloat16* Bl = g_wi_lo + (size_t)layer * GDIM * HID;

    int m0 = blockIdx.y * 128, n0 = blockIdx.x * 128;
    int tid = threadIdx.x, warp = tid >> 5, lane = tid & 31;
    int wm = (warp >> 2) * 64, wn = (warp & 3) * 32;
    int r = lane >> 2, q = lane & 3;

    float acc[4][4][4];
#pragma unroll
    for (int a = 0; a < 4; a++)
#pragma unroll
        for (int b = 0; b < 4; b++)
#pragma unroll
            for (int c = 0; c < 4; c++) acc[a][b][c] = 0.f;

    // prologue: issue k-iters 0..1
#pragma unroll
    for (int s = 0; s < PG_STG - 1; s++) {
        pg_issue(Ah, Al, Bh, Bl, sAh + s * PG_AS, sAl + s * PG_AS,
                 sBh + s * PG_BS, sBl + s * PG_BS, m0, n0, s * 32, tid);
        CP_COMMIT();
    }

    for (int it = 0; it < 32; it++) {
        CP_WAIT1();
        __syncthreads();
        int nk = it + PG_STG - 1;
        if (nk < 32) {
            int ns = nk % PG_STG;
            pg_issue(Ah, Al, Bh, Bl, sAh + ns * PG_AS, sAl + ns * PG_AS,
                     sBh + ns * PG_BS, sBl + ns * PG_BS, m0, n0, nk * 32, tid);
        }
        CP_COMMIT();

        int cs = it % PG_STG;
        const __nv_bfloat16* cAh = sAh + cs * PG_AS;
        const __nv_bfloat16* cAl = sAl + cs * PG_AS;
        const __nv_bfloat16* cBh = sBh + cs * PG_BS;
        const __nv_bfloat16* cBl = sBl + cs * PG_BS;
#pragma unroll
        for (int kk = 0; kk < 32; kk += 16) {
            unsigned ah[4][4], al[4][4], bh[4][2], bl[4][2];
#pragma unroll
            for (int mi = 0; mi < 4; mi++) {
                int rowa = wm + mi * 16 + r;
                const __nv_bfloat16* p = cAh + rowa * 40 + kk + 2 * q;
                ah[mi][0] = *(const unsigned*)p;
                ah[mi][1] = *(const unsigned*)(p + 8 * 40);
                ah[mi][2] = *(const unsigned*)(p + 8);
                ah[mi][3] = *(const unsigned*)(p + 8 * 40 + 8);
                const __nv_bfloat16* pl = cAl + rowa * 40 + kk + 2 * q;
                al[mi][0] = *(const unsigned*)pl;
                al[mi][1] = *(const unsigned*)(pl + 8 * 40);
                al[mi][2] = *(const unsigned*)(pl + 8);
                al[mi][3] = *(const unsigned*)(pl + 8 * 40 + 8);
            }
#pragma unroll
            for (int ni = 0; ni < 4; ni++) {
                int rowb = wn + ni * 8 + r;
                const __nv_bfloat16* p = cBh + rowb * 40 + kk + 2 * q;
                bh[ni][0] = *(const unsigned*)p;
                bh[ni][1] = *(const unsigned*)(p + 8);
                const __nv_bfloat16* pl = cBl + rowb * 40 + kk + 2 * q;
                bl[ni][0] = *(const unsigned*)pl;
                bl[ni][1] = *(const unsigned*)(pl + 8);
            }
#pragma unroll
            for (int mi = 0; mi < 4; mi++)
#pragma unroll
                for (int ni = 0; ni < 4; ni++) {
                    mma_bf16(acc[mi][ni], ah[mi], bh[ni]);
                    mma_bf16(acc[mi][ni], ah[mi], bl[ni]);
                    mma_bf16(acc[mi][ni], al[mi], bh[ni]);
                }
        }
    }

    const float* bias = g_bias + layer * GDIM;
#pragma unroll
    for (int mi = 0; mi < 4; mi++)
#pragma unroll
        for (int ni = 0; ni < 4; ni++) {
            int gm = m0 + wm + mi * 16 + r;
            int gn = n0 + wn + ni * 8 + 2 * q;
            float b0v = bias[gn], b1v = bias[gn + 1];
            g_gpre[(size_t)gm * GDIM + gn]           = acc[mi][ni][0] + b0v;
            g_gpre[(size_t)gm * GDIM + gn + 1]       = acc[mi][ni][1] + b1v;
            g_gpre[(size_t)(gm + 8) * GDIM + gn]     = acc[mi][ni][2] + b0v;
            g_gpre[(size_t)(gm + 8) * GDIM + gn + 1] = acc[mi][ni][3] + b1v;
        }
}

// ---------------- recurrent step -------------------------------------------------
// CTA 64(batch) x 32(gate cols); 8 warps: 4 warp-positions (16x32) x 2-way K-split
// KC=64, 3-stage cp.async, smem reduction, fused LSTM epilogue
#define ST_STG 3
#define ST_AS  (64*72)
#define ST_BS  (32*72)
#define ST_SMEM ((2*ST_STG*ST_AS + 2*ST_STG*ST_BS) * 2 + 64*33*4)

__device__ __forceinline__ void st_issue(
    const __nv_bfloat16* Ah, const __nv_bfloat16* Al,
    const __nv_bfloat16* Bh, const __nv_bfloat16* Bl,
    __nv_bfloat16* dAh, __nv_bfloat16* dAl, __nv_bfloat16* dBh, __nv_bfloat16* dBl,
    int n0, int k0, int tid)
{
#pragma unroll
    for (int i = tid; i < 512; i += 256) {
        int rr = i >> 3, c = i & 7;
        size_t go = (size_t)rr * HID + k0 + c * 8;
        int so = rr * 72 + c * 8;
        cpasync16(dAh + so, Ah + go);
        cpasync16(dAl + so, Al + go);
    }
#pragma unroll
    for (int i = tid; i < 256; i += 256) {
        int rr = i >> 3, c = i & 7;
        size_t go = (size_t)(n0 + rr) * HID + k0 + c * 8;
        int so = rr * 72 + c * 8;
        cpasync16(dBh + so, Bh + go);
        cpasync16(dBl + so, Bl + go);
    }
}

__global__ __launch_bounds__(256, 1)
void lstm_step_kernel(int layer, int t) {
    extern __shared__ char smc[];
    __nv_bfloat16* sAh = (__nv_bfloat16*)smc;
    __nv_bfloat16* sAl = sAh + ST_STG * ST_AS;
    __nv_bfloat16* sBh = sAl + ST_STG * ST_AS;
    __nv_bfloat16* sBl = sBh + ST_STG * ST_BS;
    float* sG = (float*)(smc + (2 * ST_STG * ST_AS + 2 * ST_STG * ST_BS) * 2);

    int n0 = blockIdx.x * 32;
    int tid = threadIdx.x, warp = tid >> 5, lane = tid & 31;
    int ws = warp >> 2;            // K-split half
    int wm = (warp & 3) * 16;      // warp m-position (16 rows)
    int r = lane >> 2, q = lane & 3;

    float acc[4][4];
#pragma unroll
    for (int a = 0; a < 4; a++)
#pragma unroll
        for (int c = 0; c < 4; c++) acc[a][c] = 0.f;

    if (t > 0) {
        const __nv_bfloat16* Ah = g_sh[layer & 1] + (size_t)(t - 1) * BATCH * HID;
        const __nv_bfloat16* Al = g_sl[layer & 1] + (size_t)(t - 1) * BATCH * HID;
        const __nv_bfloat16* Bh = g_wh_hi + (size_t)layer * GDIM * HID;
        const __nv_bfloat16* Bl = g_wh_lo + (size_t)layer * GDIM * HID;

#pragma unroll
        for (int s = 0; s < ST_STG - 1; s++) {
            st_issue(Ah, Al, Bh, Bl, sAh + s * ST_AS, sAl + s * ST_AS,
                     sBh + s * ST_BS, sBl + s * ST_BS, n0, s * 64, tid);
            CP_COMMIT();
        }

        for (int it = 0; it < 16; it++) {
            CP_WAIT1();
            __syncthreads();
            int nk = it + ST_STG - 1;
            if (nk < 16) {
                int ns = nk % ST_STG;
                st_issue(Ah, Al, Bh, Bl, sAh + ns * ST_AS, sAl + ns * ST_AS,
                         sBh + ns * ST_BS, sBl + ns * ST_BS, n0, nk * 64, tid);
            }
            CP_COMMIT();

            int cs = it % ST_STG;
            const __nv_bfloat16* cAh = sAh + cs * ST_AS;
            const __nv_bfloat16* cAl = sAl + cs * ST_AS;
            const __nv_bfloat16* cBh = sBh + cs * ST_BS;
            const __nv_bfloat16* cBl = sBl + cs * ST_BS;
#pragma unroll
            for (int kh = 0; kh < 2; kh++) {
                int kk = ws * 32 + kh * 16;
                unsigned a_h[4], a_l[4], b_h[4][2], b_l[4][2];
                int rowa = wm + r;
                const __nv_bfloat16* p = cAh + rowa * 72 + kk + 2 * q;
                a_h[0] = *(const unsigned*)p;
                a_h[1] = *(const unsigned*)(p + 8 * 72);
                a_h[2] = *(const unsigned*)(p + 8);
                a_h[3] = *(const unsigned*)(p + 8 * 72 + 8);
                const __nv_bfloat16* pl = cAl + rowa * 72 + kk + 2 * q;
                a_l[0] = *(const unsigned*)pl;
                a_l[1] = *(const unsigned*)(pl + 8 * 72);
                a_l[2] = *(const unsigned*)(pl + 8);
                a_l[3] = *(const unsigned*)(pl + 8 * 72 + 8);
#pragma unroll
                for (int ni = 0; ni < 4; ni++) {
                    int rowb = ni * 8 + r;
                    const __nv_bfloat16* pb = cBh + rowb * 72 + kk + 2 * q;
                    b_h[ni][0] = *(const unsigned*)pb;
                    b_h[ni][1] = *(const unsigned*)(pb + 8);
                    const __nv_bfloat16* pbl = cBl + rowb * 72 + kk + 2 * q;
                    b_l[ni][0] = *(const unsigned*)pbl;
                    b_l[ni][1] = *(const unsigned*)(pbl + 8);
                }
#pragma unroll
                for (int ni = 0; ni < 4; ni++) {
                    mma_bf16(acc[ni], a_h, b_h[ni]);
                    mma_bf16(acc[ni], a_h, b_l[ni]);
                    mma_bf16(acc[ni], a_l, b_h[ni]);
                }
            }
        }
    }

    // K-split reduction via sG
    if (ws == 1) {
#pragma unroll
        for (int ni = 0; ni < 4; ni++) {
            int col = ni * 8 + 2 * q;
            sG[(wm + r) * 33 + col]         = acc[ni][0];
            sG[(wm + r) * 33 + col + 1]     = acc[ni][1];
            sG[(wm + r + 8) * 33 + col]     = acc[ni][2];
            sG[(wm + r + 8) * 33 + col + 1] = acc[ni][3];
        }
    }
    __syncthreads();
    if (ws == 0) {
#pragma unroll
        for (int ni = 0; ni < 4; ni++) {
            int col = ni * 8 + 2 * q;
            sG[(wm + r) * 33 + col]         += acc[ni][0];
            sG[(wm + r) * 33 + col + 1]     += acc[ni][1];
            sG[(wm + r + 8) * 33 + col]     += acc[ni][2];
            sG[(wm + r + 8) * 33 + col + 1] += acc[ni][3];
        }
    }
    __syncthreads();

    // fused LSTM elementwise: this CTA owns hidden units [n0/4, n0/4+8)
    const float* gpre = g_gpre + (size_t)t * BATCH * GDIM;
    __nv_bfloat16* oh = g_sh[layer & 1] + (size_t)t * BATCH * HID;
    __nv_bfloat16* ol = g_sl[layer & 1] + (size_t)t * BATCH * HID;
#pragma unroll
    for (int i = tid; i < 512; i += 256) {
        int b_ = i >> 3, u = i & 7;
        int colb = u * 4;
        float4 gp = *(const float4*)(gpre + (size_t)b_ * GDIM + n0 + colb);
        float gi = sG[b_ * 33 + colb + 0] + gp.x;
        float gf = sG[b_ * 33 + colb + 1] + gp.y;
        float gg = sG[b_ * 33 + colb + 2] + gp.z;
        float go = sG[b_ * 33 + colb + 3] + gp.w;
        int unit = (n0 >> 2) + u;
        float cold = (t == 0) ? 0.f : g_c[b_ * HID + unit];
        float si = 1.f / (1.f + expf(-gi));
        float sf = 1.f / (1.f + expf(-gf));
        float so = 1.f / (1.f + expf(-go));
        float cn = sf * cold + si * tanhf(gg);
        float hn = so * tanhf(cn);
        g_c[b_ * HID + unit] = cn;
        __nv_bfloat16 hh = __float2bfloat16(hn);
        oh[(size_t)b_ * HID + unit] = hh;
        ol[(size_t)b_ * HID + unit] = __float2bfloat16(hn - __bfloat162float(hh));
    }
}

// ---------------- finalize ------------------------------------------------------
__global__ void finalize_kernel(float* __restrict__ out) {
    int i = blockIdx.x * 256 + threadIdx.x;
    if (i < BATCH * HID) {
        size_t o = (size_t)(NSTEP - 1) * BATCH * HID + i;
        float hv = __bfloat162float(g_sh[(NLAYER - 1) & 1][o]) +
                   __bfloat162float(g_sl[(NLAYER - 1) & 1][o]);
        out[i] = hv;
        out[BATCH * HID + i] = hv;
        out[2 * BATCH * HID + i] = g_c[i];
    }
}

// ---------------- launch --------------------------------------------------------
extern "C" void kernel_launch(void* const* d_in, const int* in_sizes, int n_in,
                              void* d_out, int out_size) {
    (void)in_sizes; (void)n_in; (void)out_size;
    const float* inputs = (const float*)d_in[0];
    const float* Wi     = (const float*)d_in[1];
    const float* Wh     = (const float*)d_in[2];
    const float* bv     = (const float*)d_in[3];

    cudaFuncSetAttribute(pregemm_kernel,
                         cudaFuncAttributeMaxDynamicSharedMemorySize, PG_SMEM);
    cudaFuncSetAttribute(lstm_step_kernel,
                         cudaFuncAttributeMaxDynamicSharedMemorySize, ST_SMEM);

    dim3 pb(32, 32, 1);
    dim3 pg(GDIM / 32, HID / 32, NLAYER * 2);
    prep_weights_kernel<<<pg, pb>>>(Wi, Wh);
    prep_bias_kernel<<<(NLAYER * GDIM + 255) / 256, 256>>>(bv);
    split_input_kernel<<<(TBROWS * HID + 255) / 256, 256>>>(inputs);

    for (int l = 0; l < NLAYER; l++) {
        pregemm_kernel<<<dim3(GDIM / 128, TBROWS / 128), 256, PG_SMEM>>>(l);
        for (int t = 0; t < NSTEP; t++)
            lstm_step_kernel<<<GDIM / 32, 256, ST_SMEM>>>(l, t);
    }
    finalize_kernel<<<(BATCH * HID + 255) / 256, 256>>>((float*)d_out);
}

// round 3
// speedup vs baseline: 2.3335x; 1.4924x over previous
#include <cuda_runtime.h>
#include <cuda_bf16.h>

#define NLAYER 4
#define HID    1024
#define BATCH  64
#define NSTEP  128
#define GDIM   4096              // 4*HID
#define TBROWS (NSTEP*BATCH)     // 8192
#define NCTA   128               // persistent grid (GDIM/32)

// ---------------- device scratch ----------------
__device__ __nv_bfloat16 g_wi_hi[(size_t)NLAYER*GDIM*HID];
__device__ __nv_bfloat16 g_wi_lo[(size_t)NLAYER*GDIM*HID];
__device__ __nv_bfloat16 g_wh_hi[(size_t)NLAYER*GDIM*HID];
__device__ __nv_bfloat16 g_wh_lo[(size_t)NLAYER*GDIM*HID];
__device__ float g_bias[NLAYER*GDIM];
__device__ float g_gpre[(size_t)TBROWS*GDIM];
__device__ __nv_bfloat16 g_xh[(size_t)TBROWS*HID];    // split input
__device__ __nv_bfloat16 g_xl[(size_t)TBROWS*HID];
__device__ __nv_bfloat16 g_sh[2][(size_t)TBROWS*HID]; // split h rowmajor (ping-pong by layer)
__device__ __nv_bfloat16 g_sl[2][(size_t)TBROWS*HID];
__device__ float g_c[BATCH*HID];
__device__ unsigned g_hfrag[2][65536];                // h in frag layout, ping-pong by step
__device__ int g_bar[NLAYER][NSTEP];                  // grid barrier counters

// ---------------- helpers ----------------
__device__ __forceinline__ void mma_bf16(float (&c)[4], const unsigned (&a)[4],
                                         const unsigned (&b)[2]) {
    asm volatile(
        "mma.sync.aligned.m16n8k16.row.col.f32.bf16.bf16.f32 "
        "{%0,%1,%2,%3}, {%4,%5,%6,%7}, {%8,%9}, {%0,%1,%2,%3};\n"
        : "+f"(c[0]), "+f"(c[1]), "+f"(c[2]), "+f"(c[3])
        : "r"(a[0]), "r"(a[1]), "r"(a[2]), "r"(a[3]), "r"(b[0]), "r"(b[1]));
}

__device__ __forceinline__ void cpasync16(__nv_bfloat16* sptr, const __nv_bfloat16* gptr) {
    unsigned s = (unsigned)__cvta_generic_to_shared(sptr);
    asm volatile("cp.async.cg.shared.global [%0], [%1], 16;\n" :: "r"(s), "l"(gptr));
}
#define CP_COMMIT() asm volatile("cp.async.commit_group;\n")
#define CP_WAIT1()  asm volatile("cp.async.wait_group 1;\n")
#define CP_WAIT0()  asm volatile("cp.async.wait_group 0;\n")

__device__ __forceinline__ void ldsm4(unsigned& r0, unsigned& r1, unsigned& r2, unsigned& r3,
                                      unsigned addr) {
    asm volatile("ldmatrix.sync.aligned.m8n8.x4.shared.b16 {%0,%1,%2,%3}, [%4];"
                 : "=r"(r0), "=r"(r1), "=r"(r2), "=r"(r3) : "r"(addr));
}

__device__ __forceinline__ unsigned ldg_cg(const unsigned* p) {
    unsigned v;
    asm volatile("ld.global.cg.b32 %0, [%1];" : "=r"(v) : "l"(p));
    return v;
}

// ---------------- weight prep ----------------
__global__ void prep_weights_kernel(const float* __restrict__ Wi,
                                    const float* __restrict__ Wh) {
    __shared__ float tile[32][33];
    int l = blockIdx.z & 3;
    int which = blockIdx.z >> 2;
    const float* W = which ? Wh : Wi;
    __nv_bfloat16* ohi = which ? g_wh_hi : g_wi_hi;
    __nv_bfloat16* olo = which ? g_wh_lo : g_wi_lo;
    int j0 = blockIdx.x * 32, k0 = blockIdx.y * 32;
    int tx = threadIdx.x, ty = threadIdx.y;
    tile[ty][tx] = W[(size_t)(l * HID + k0 + ty) * GDIM + j0 + tx];
    __syncthreads();
    float v = tile[tx][ty];
    int j = j0 + ty;
    int gate = j >> 10, unit = j & 1023;
    int jp = unit * 4 + gate;
    __nv_bfloat16 hi = __float2bfloat16(v);
    float lov = v - __bfloat162float(hi);
    size_t o = (size_t)(l * GDIM + jp) * HID + (k0 + tx);
    ohi[o] = hi;
    olo[o] = __float2bfloat16(lov);
}

__global__ void prep_bias_kernel(const float* __restrict__ b) {
    int i = blockIdx.x * 256 + threadIdx.x;
    if (i < NLAYER * GDIM) {
        int l = i >> 12, j = i & 4095;
        int gate = j >> 10, unit = j & 1023;
        g_bias[l * GDIM + unit * 4 + gate] = b[i];
    }
}

__global__ void split_input_kernel(const float* __restrict__ X) {
    int i = blockIdx.x * 256 + threadIdx.x;
    if (i < TBROWS * HID) {
        float v = X[i];
        __nv_bfloat16 hi = __float2bfloat16(v);
        g_xh[i] = hi;
        g_xl[i] = __float2bfloat16(v - __bfloat162float(hi));
    }
}

__global__ void zero_bar_kernel() {
    int i = blockIdx.x * 256 + threadIdx.x;
    if (i < NLAYER * NSTEP) ((int*)g_bar)[i] = 0;
}

// ---------------- pre-GEMM (unchanged from R2) ----------------
#define PG_STG 3
#define PG_AS  (128*40)
#define PG_BS  (128*40)
#define PG_SMEM ((2*PG_STG*PG_AS + 2*PG_STG*PG_BS) * 2)

__device__ __forceinline__ void pg_issue(
    const __nv_bfloat16* Ah, const __nv_bfloat16* Al,
    const __nv_bfloat16* Bh, const __nv_bfloat16* Bl,
    __nv_bfloat16* dAh, __nv_bfloat16* dAl, __nv_bfloat16* dBh, __nv_bfloat16* dBl,
    int m0, int n0, int k0, int tid)
{
#pragma unroll
    for (int i = tid; i < 512; i += 256) {
        int rr = i >> 2, c = i & 3;
        size_t go = (size_t)(m0 + rr) * HID + k0 + c * 8;
        int so = rr * 40 + c * 8;
        cpasync16(dAh + so, Ah + go);
        cpasync16(dAl + so, Al + go);
    }
#pragma unroll
    for (int i = tid; i < 512; i += 256) {
        int rr = i >> 2, c = i & 3;
        size_t go = (size_t)(n0 + rr) * HID + k0 + c * 8;
        int so = rr * 40 + c * 8;
        cpasync16(dBh + so, Bh + go);
        cpasync16(dBl + so, Bl + go);
    }
}

__global__ __launch_bounds__(256, 1)
void pregemm_kernel(int layer) {
    extern __shared__ __nv_bfloat16 sm[];
    __nv_bfloat16* sAh = sm;
    __nv_bfloat16* sAl = sAh + PG_STG * PG_AS;
    __nv_bfloat16* sBh = sAl + PG_STG * PG_AS;
    __nv_bfloat16* sBl = sBh + PG_STG * PG_BS;

    const __nv_bfloat16 *Ah, *Al;
    if (layer == 0) { Ah = g_xh; Al = g_xl; }
    else { Ah = g_sh[(layer - 1) & 1]; Al = g_sl[(layer - 1) & 1]; }
    const __nv_bfloat16* Bh = g_wi_hi + (size_t)layer * GDIM * HID;
    const __nv_bfloat16* Bl = g_wi_lo + (size_t)layer * GDIM * HID;

    int m0 = blockIdx.y * 128, n0 = blockIdx.x * 128;
    int tid = threadIdx.x, warp = tid >> 5, lane = tid & 31;
    int wm = (warp >> 2) * 64, wn = (warp & 3) * 32;
    int r = lane >> 2, q = lane & 3;

    float acc[4][4][4];
#pragma unroll
    for (int a = 0; a < 4; a++)
#pragma unroll
        for (int b = 0; b < 4; b++)
#pragma unroll
            for (int c = 0; c < 4; c++) acc[a][b][c] = 0.f;

#pragma unroll
    for (int s = 0; s < PG_STG - 1; s++) {
        pg_issue(Ah, Al, Bh, Bl, sAh + s * PG_AS, sAl + s * PG_AS,
                 sBh + s * PG_BS, sBl + s * PG_BS, m0, n0, s * 32, tid);
        CP_COMMIT();
    }

    for (int it = 0; it < 32; it++) {
        CP_WAIT1();
        __syncthreads();
        int nk = it + PG_STG - 1;
        if (nk < 32) {
            int ns = nk % PG_STG;
            pg_issue(Ah, Al, Bh, Bl, sAh + ns * PG_AS, sAl + ns * PG_AS,
                     sBh + ns * PG_BS, sBl + ns * PG_BS, m0, n0, nk * 32, tid);
        }
        CP_COMMIT();

        int cs = it % PG_STG;
        const __nv_bfloat16* cAh = sAh + cs * PG_AS;
        const __nv_bfloat16* cAl = sAl + cs * PG_AS;
        const __nv_bfloat16* cBh = sBh + cs * PG_BS;
        const __nv_bfloat16* cBl = sBl + cs * PG_BS;
#pragma unroll
        for (int kk = 0; kk < 32; kk += 16) {
            unsigned ah[4][4], al[4][4], bh[4][2], bl[4][2];
#pragma unroll
            for (int mi = 0; mi < 4; mi++) {
                int rowa = wm + mi * 16 + r;
                const __nv_bfloat16* p = cAh + rowa * 40 + kk + 2 * q;
                ah[mi][0] = *(const unsigned*)p;
                ah[mi][1] = *(const unsigned*)(p + 8 * 40);
                ah[mi][2] = *(const unsigned*)(p + 8);
                ah[mi][3] = *(const unsigned*)(p + 8 * 40 + 8);
                const __nv_bfloat16* pl = cAl + rowa * 40 + kk + 2 * q;
                al[mi][0] = *(const unsigned*)pl;
                al[mi][1] = *(const unsigned*)(pl + 8 * 40);
                al[mi][2] = *(const unsigned*)(pl + 8);
                al[mi][3] = *(const unsigned*)(pl + 8 * 40 + 8);
            }
#pragma unroll
            for (int ni = 0; ni < 4; ni++) {
                int rowb = wn + ni * 8 + r;
                const __nv_bfloat16* p = cBh + rowb * 40 + kk + 2 * q;
                bh[ni][0] = *(const unsigned*)p;
                bh[ni][1] = *(const unsigned*)(p + 8);
                const __nv_bfloat16* pl = cBl + rowb * 40 + kk + 2 * q;
                bl[ni][0] = *(const unsigned*)pl;
                bl[ni][1] = *(const unsigned*)(pl + 8);
            }
#pragma unroll
            for (int mi = 0; mi < 4; mi++)
#pragma unroll
                for (int ni = 0; ni < 4; ni++) {
                    mma_bf16(acc[mi][ni], ah[mi], bh[ni]);
                    mma_bf16(acc[mi][ni], ah[mi], bl[ni]);
                    mma_bf16(acc[mi][ni], al[mi], bh[ni]);
                }
        }
    }

    const float* bias = g_bias + layer * GDIM;
#pragma unroll
    for (int mi = 0; mi < 4; mi++)
#pragma unroll
        for (int ni = 0; ni < 4; ni++) {
            int gm = m0 + wm + mi * 16 + r;
            int gn = n0 + wn + ni * 8 + 2 * q;
            float b0v = bias[gn], b1v = bias[gn + 1];
            g_gpre[(size_t)gm * GDIM + gn]           = acc[mi][ni][0] + b0v;
            g_gpre[(size_t)gm * GDIM + gn + 1]       = acc[mi][ni][1] + b1v;
            g_gpre[(size_t)(gm + 8) * GDIM + gn]     = acc[mi][ni][2] + b0v;
            g_gpre[(size_t)(gm + 8) * GDIM + gn + 1] = acc[mi][ni][3] + b1v;
        }
}

// ---------------- persistent per-layer sequence kernel --------------------------
// 128 CTAs x 256 thr. CTA owns 32 gate-cols (8 hidden units) for all 128 steps.
// Weights resident in smem (ldmatrix). h exchanged in frag layout via global (LDG.cg).
// 8 warps = 2 batch-halves (p) x 4-way K-split (ws). Warp tile 32b x 32g x 256k.
#define WSTR 1032                              // weight smem row stride (elems)
#define SEQ_SMEM (2*32*WSTR*2 + 4*64*36*4)     // 132096 + 36864 = 168960 B

__global__ __launch_bounds__(256, 1)
void lstm_seq_kernel(int layer, int lastLayer) {
    extern __shared__ char smc[];
    __nv_bfloat16* wsm_h = (__nv_bfloat16*)smc;                // [32][WSTR]
    __nv_bfloat16* wsm_l = wsm_h + 32 * WSTR;
    float* sG = (float*)(smc + 2 * 32 * WSTR * 2);             // [4][64][36]

    int tid = threadIdx.x, warp = tid >> 5, lane = tid & 31;
    int ws = warp & 3, p = warp >> 2;          // k-split quarter, batch half
    int r = lane >> 2, q = lane & 3;
    int cta = blockIdx.x;
    int n0 = cta * 32;                          // gate-col base
    int u0 = cta * 8;                           // hidden-unit base

    // ---- load Wh tile (32 rows x 1024, hi+lo) into smem ----
    {
        const __nv_bfloat16* Wh = g_wh_hi + ((size_t)layer * GDIM + n0) * HID;
        const __nv_bfloat16* Wl = g_wh_lo + ((size_t)layer * GDIM + n0) * HID;
#pragma unroll
        for (int i = tid; i < 4096; i += 256) {
            int rr = i >> 7, cc = (i & 127) * 8;
            cpasync16(wsm_h + rr * WSTR + cc, Wh + (size_t)rr * HID + cc);
            cpasync16(wsm_l + rr * WSTR + cc, Wl + (size_t)rr * HID + cc);
        }
        CP_COMMIT();
        CP_WAIT0();
        __syncthreads();
    }

    // ---- precompute ldmatrix lane addresses for B frags ----
    // pair01: tiles (ni0,k0)(ni0,k+8)(ni1,k0)(ni1,k+8); pair23: rows +16
    int trow = ((lane >> 4) << 3) + (lane & 7);
    int tk8  = ((lane >> 3) & 1) * 8;
    unsigned b01h = (unsigned)__cvta_generic_to_shared(wsm_h + trow * WSTR + 16 * ws + tk8);
    unsigned b23h = b01h + 16 * WSTR * 2;
    unsigned b01l = (unsigned)__cvta_generic_to_shared(wsm_l + trow * WSTR + 16 * ws + tk8);
    unsigned b23l = b01l + 16 * WSTR * 2;

    // frag-buffer lane offset for this warp
    int fo = (ws * 2 + p) * 512 + lane;

    // epilogue thread mapping
    int eb = tid >> 2, eq = tid & 3;            // batch, unit-pair
    float c0 = 0.f, c1 = 0.f;                   // cell state registers
    // epilogue frag-write coords
    int w_mi = (eb >> 4) & 1, w_rp = (eb >> 3) & 1, w_p = eb >> 5;
    int w_lane = (eb & 7) * 4 + eq;
    int w_c = u0 >> 6, w_ws = (u0 >> 4) & 3, w_half = (u0 >> 3) & 1;
    int w_j = w_mi * 4 + w_half * 2 + w_rp;
    unsigned w_off = (unsigned)(w_c * 4096 + ((w_ws * 2 + w_p) * 16 + w_j) * 32 + w_lane);

    __nv_bfloat16* rm_h = g_sh[layer & 1];
    __nv_bfloat16* rm_l = g_sl[layer & 1];

    for (int t = 0; t < NSTEP; t++) {
        float acc[2][4][4];
#pragma unroll
        for (int a = 0; a < 2; a++)
#pragma unroll
            for (int b = 0; b < 4; b++)
#pragma unroll
                for (int c = 0; c < 4; c++) acc[a][b][c] = 0.f;

        if (t > 0) {
            const unsigned* fb = g_hfrag[(t - 1) & 1] + fo;
            unsigned abuf[2][16];
#pragma unroll
            for (int j = 0; j < 16; j++) abuf[0][j] = ldg_cg(fb + j * 32);

#pragma unroll
            for (int c = 0; c < 16; c++) {
                const unsigned* a = abuf[c & 1];
                if (c < 15) {
                    const unsigned* fn = fb + (c + 1) * 4096;
                    unsigned* d = abuf[(c + 1) & 1];
#pragma unroll
                    for (int j = 0; j < 16; j++) d[j] = ldg_cg(fn + j * 32);
                }
                unsigned bh[4][2], bl[4][2];
                ldsm4(bh[0][0], bh[0][1], bh[1][0], bh[1][1], b01h + c * 128);
                ldsm4(bh[2][0], bh[2][1], bh[3][0], bh[3][1], b23h + c * 128);
                ldsm4(bl[0][0], bl[0][1], bl[1][0], bl[1][1], b01l + c * 128);
                ldsm4(bl[2][0], bl[2][1], bl[3][0], bl[3][1], b23l + c * 128);
#pragma unroll
                for (int mi = 0; mi < 2; mi++) {
                    const unsigned (&ah)[4] = *(const unsigned(*)[4])(a + 4 * mi);
                    const unsigned (&al)[4] = *(const unsigned(*)[4])(a + 8 + 4 * mi);
#pragma unroll
                    for (int ni = 0; ni < 4; ni++) {
                        mma_bf16(acc[mi][ni], ah, bh[ni]);
                        mma_bf16(acc[mi][ni], ah, bl[ni]);
                        mma_bf16(acc[mi][ni], al, bh[ni]);
                    }
                }
            }

            // dump accumulators to this warp's k-split slab
            float* slab = sG + ws * (64 * 36);
#pragma unroll
            for (int mi = 0; mi < 2; mi++)
#pragma unroll
                for (int ni = 0; ni < 4; ni++) {
                    int row = p * 32 + mi * 16 + r;
                    int col = ni * 8 + 2 * q;
                    *(float2*)&slab[row * 36 + col] =
                        make_float2(acc[mi][ni][0], acc[mi][ni][1]);
                    *(float2*)&slab[(row + 8) * 36 + col] =
                        make_float2(acc[mi][ni][2], acc[mi][ni][3]);
                }
        }
        __syncthreads();

        // ---- fused LSTM epilogue: thread (eb, eq) -> units u0+2eq, u0+2eq+1 ----
        {
            const float* gp = g_gpre + ((size_t)(t * BATCH + eb)) * GDIM + n0 + 8 * eq;
            float4 G0 = *(const float4*)gp;
            float4 G1 = *(const float4*)(gp + 4);
            float g0 = G0.x, g1 = G0.y, g2 = G0.z, g3 = G0.w;
            float g4 = G1.x, g5 = G1.y, g6 = G1.z, g7 = G1.w;
            if (t > 0) {
#pragma unroll
                for (int s = 0; s < 4; s++) {
                    const float* sl = sG + s * (64 * 36) + eb * 36 + 8 * eq;
                    float4 v0 = *(const float4*)sl;
                    float4 v1 = *(const float4*)(sl + 4);
                    g0 += v0.x; g1 += v0.y; g2 += v0.z; g3 += v0.w;
                    g4 += v1.x; g5 += v1.y; g6 += v1.z; g7 += v1.w;
                }
            }
            // unit A: gates g0..g3 (i,f,g,o); unit B: g4..g7
            float siA = 1.f / (1.f + expf(-g0));
            float sfA = 1.f / (1.f + expf(-g1));
            float soA = 1.f / (1.f + expf(-g3));
            float cnA = sfA * c0 + siA * tanhf(g2);
            float hnA = soA * tanhf(cnA);
            float siB = 1.f / (1.f + expf(-g4));
            float sfB = 1.f / (1.f + expf(-g5));
            float soB = 1.f / (1.f + expf(-g7));
            float cnB = sfB * c1 + siB * tanhf(g6);
            float hnB = soB * tanhf(cnB);
            c0 = cnA; c1 = cnB;

            __nv_bfloat16 hA = __float2bfloat16(hnA);
            __nv_bfloat16 hB = __float2bfloat16(hnB);
            __nv_bfloat16 lA = __float2bfloat16(hnA - __bfloat162float(hA));
            __nv_bfloat16 lB = __float2bfloat16(hnB - __bfloat162float(hB));

            // rowmajor split h (for next layer's pregemm / finalize)
            size_t ro = (size_t)(t * BATCH + eb) * HID + u0 + 2 * eq;
            *(__nv_bfloat162*)(rm_h + ro) = __nv_bfloat162(hA, hB);
            *(__nv_bfloat162*)(rm_l + ro) = __nv_bfloat162(lA, lB);

            // frag-layout h (for next step's MMA)
            unsigned* fw = g_hfrag[t & 1] + w_off;
            unsigned wh_, wl_;
            {
                __nv_bfloat162 th = __nv_bfloat162(hA, hB);
                __nv_bfloat162 tl = __nv_bfloat162(lA, lB);
                wh_ = *(unsigned*)&th;
                wl_ = *(unsigned*)&tl;
            }
            fw[0]      = wh_;
            fw[8 * 32] = wl_;

            if (lastLayer && t == NSTEP - 1)
                *(float2*)(g_c + eb * HID + u0 + 2 * eq) = make_float2(cnA, cnB);
        }

        // ---- grid barrier (all 128 CTAs resident) ----
        if (t < NSTEP - 1) {
            __syncthreads();
            if (tid == 0) {
                __threadfence();
                atomicAdd(&g_bar[layer][t], 1);
                while (*(volatile int*)&g_bar[layer][t] < NCTA) __nanosleep(32);
                __threadfence();
            }
            __syncthreads();
        }
    }
}

// ---------------- finalize ------------------------------------------------------
__global__ void finalize_kernel(float* __restrict__ out) {
    int i = blockIdx.x * 256 + threadIdx.x;
    if (i < BATCH * HID) {
        size_t o = (size_t)(NSTEP - 1) * BATCH * HID + i;
        float hv = __bfloat162float(g_sh[(NLAYER - 1) & 1][o]) +
                   __bfloat162float(g_sl[(NLAYER - 1) & 1][o]);
        out[i] = hv;
        out[BATCH * HID + i] = hv;
        out[2 * BATCH * HID + i] = g_c[i];
    }
}

// ---------------- launch --------------------------------------------------------
extern "C" void kernel_launch(void* const* d_in, const int* in_sizes, int n_in,
                              void* d_out, int out_size) {
    (void)in_sizes; (void)n_in; (void)out_size;
    const float* inputs = (const float*)d_in[0];
    const float* Wi     = (const float*)d_in[1];
    const float* Wh     = (const float*)d_in[2];
    const float* bv     = (const float*)d_in[3];

    cudaFuncSetAttribute(pregemm_kernel,
                         cudaFuncAttributeMaxDynamicSharedMemorySize, PG_SMEM);
    cudaFuncSetAttribute(lstm_seq_kernel,
                         cudaFuncAttributeMaxDynamicSharedMemorySize, SEQ_SMEM);

    dim3 pb(32, 32, 1);
    dim3 pg(GDIM / 32, HID / 32, NLAYER * 2);
    prep_weights_kernel<<<pg, pb>>>(Wi, Wh);
    prep_bias_kernel<<<(NLAYER * GDIM + 255) / 256, 256>>>(bv);
    split_input_kernel<<<(TBROWS * HID + 255) / 256, 256>>>(inputs);
    zero_bar_kernel<<<2, 256>>>();

    for (int l = 0; l < NLAYER; l++) {
        pregemm_kernel<<<dim3(GDIM / 128, TBROWS / 128), 256, PG_SMEM>>>(l);
        lstm_seq_kernel<<<NCTA, 256, SEQ_SMEM>>>(l, l == NLAYER - 1);
    }
    finalize_kernel<<<(BATCH * HID + 255) / 256, 256>>>((float*)d_out);
}